// round 6
// baseline (speedup 1.0000x reference)
#include <cuda_runtime.h>
#include <math.h>

#define OUT_COLS 2883

// scratch: batch-0 features transposed to [H,W,C], concatenated per scale
__device__ float g_scratch[376320];
// consts: [0..8] Minv[d][k], [9..11] o0; per view v at 12+v*12: c[v][k][d], o_v at +9..11
__device__ float g_consts[12 + 3 * 12];

// Fused: feature transpose (all blocks) + camera constants (block 0, threads 0-2)
__global__ void prep_kernel(const float* __restrict__ f0,
                            const float* __restrict__ f1,
                            const float* __restrict__ f2,
                            const float* __restrict__ f3,
                            const float* __restrict__ cameras) {
    if (blockIdx.x == 0 && threadIdx.x < 3) {
        const float PIF = 3.14159274101257324f;
        int v = threadIdx.x;
        float th = cameras[v * 5 + 0] * (PIF / 180.0f);
        float ph = cameras[v * 5 + 1] * (PIF / 180.0f);
        float r  = cameras[v * 5 + 3];
        float camy = r * sinf(ph);
        float lens = r * cosf(ph);
        float camx = lens * cosf(th);
        float camz = lens * sinf(th);
        float Z[3] = {camx, camy, camz};
        float Y[3] = {camy * cosf(th + PIF), lens, camy * sinf(th + PIF)};
        float X[3] = {Y[1] * Z[2] - Y[2] * Z[1],
                      Y[2] * Z[0] - Y[0] * Z[2],
                      Y[0] * Z[1] - Y[1] * Z[0]};
        float nx = sqrtf(X[0]*X[0] + X[1]*X[1] + X[2]*X[2]);
        float ny = sqrtf(Y[0]*Y[0] + Y[1]*Y[1] + Y[2]*Y[2]);
        float nz = sqrtf(Z[0]*Z[0] + Z[1]*Z[1] + Z[2]*Z[2]);
        float cn[3][3];
        for (int d = 0; d < 3; d++) {
            cn[0][d] = X[d] / nx;
            cn[1][d] = Y[d] / ny;
            cn[2][d] = Z[d] / nz;
        }
        for (int k = 0; k < 3; k++)
            for (int d = 0; d < 3; d++)
                g_consts[12 + v * 12 + k * 3 + d] = cn[k][d];
        for (int d = 0; d < 3; d++)
            g_consts[12 + v * 12 + 9 + d] = Z[d];

        if (v == 0) {
            double A[3][3];
            for (int i = 0; i < 3; i++)
                for (int j = 0; j < 3; j++)
                    A[i][j] = (double)cn[j][i];
            double det = A[0][0] * (A[1][1]*A[2][2] - A[1][2]*A[2][1])
                       + A[0][1] * (A[1][2]*A[2][0] - A[1][0]*A[2][2])
                       + A[0][2] * (A[1][0]*A[2][1] - A[1][1]*A[2][0]);
            double inv[3][3];
            inv[0][0] = (A[1][1]*A[2][2] - A[1][2]*A[2][1]) / det;
            inv[0][1] = (A[0][2]*A[2][1] - A[0][1]*A[2][2]) / det;
            inv[0][2] = (A[0][1]*A[1][2] - A[0][2]*A[1][1]) / det;
            inv[1][0] = (A[1][2]*A[2][0] - A[1][0]*A[2][2]) / det;
            inv[1][1] = (A[0][0]*A[2][2] - A[0][2]*A[2][0]) / det;
            inv[1][2] = (A[0][2]*A[1][0] - A[0][0]*A[1][2]) / det;
            inv[2][0] = (A[1][0]*A[2][1] - A[1][1]*A[2][0]) / det;
            inv[2][1] = (A[0][1]*A[2][0] - A[0][0]*A[2][1]) / det;
            inv[2][2] = (A[0][0]*A[1][1] - A[0][1]*A[1][0]) / det;
            for (int d = 0; d < 3; d++)
                for (int k = 0; k < 3; k++)
                    g_consts[d * 3 + k] = (float)inv[d][k];
            for (int d = 0; d < 3; d++)
                g_consts[9 + d] = Z[d];
        }
    }

    int i = blockIdx.x * blockDim.x + threadIdx.x;
    if (i >= 376320) return;
    float v;
    if (i < 200704)      { int c = i & 63;  int p = i >> 6;                 v = f0[c * 3136 + p]; }
    else if (i < 301056) { int l = i - 200704; int c = l & 127; int p = l >> 7; v = f1[c * 784 + p]; }
    else if (i < 351232) { int l = i - 301056; int c = l & 255; int p = l >> 8; v = f2[c * 196 + p]; }
    else                 { int l = i - 351232; int c = l & 511; int p = l >> 9; v = f3[c * 49 + p]; }
    g_scratch[i] = v;
}

__global__ __launch_bounds__(256) void main_kernel(const float* __restrict__ inputs,
                                                   float* __restrict__ out) {
    // Row staging buffer: 4-float front pad (for head shift) + 2883 + round up.
    __shared__ __align__(16) float buf[4 + 2884];
    __shared__ int sbase[3][4];
    __shared__ float sinp[3];

    int row = blockIdx.x;
    int tid = threadIdx.x;
    size_t base = (size_t)row * OUT_COLS;
    // head: floats until the first 16B-aligned index >= base. base%4 == (3*row)%4.
    int head = (int)((4 - (base & 3)) & 3);

    if (tid < 3) {
        int v = tid;
        float in0 = inputs[row * 3 + 0];
        float in1 = inputs[row * 3 + 1];
        float in2 = inputs[row * 3 + 2];
        const float* C = g_consts;
        float po[3];
        #pragma unroll
        for (int k = 0; k < 3; k++)
            po[k] = fmaf(in0, C[0 * 3 + k],
                    fmaf(in1, C[1 * 3 + k],
                    fmaf(in2, C[2 * 3 + k], C[9 + k])));
        const float* cv = C + 12 + v * 12;
        float d0 = po[0] - cv[9];
        float d1 = po[1] - cv[10];
        float d2 = po[2] - cv[11];
        float X = fmaf(d0, cv[0], fmaf(d1, cv[1], d2 * cv[2]));
        float Y = fmaf(d0, cv[3], fmaf(d1, cv[4], d2 * cv[5]));
        float Z = fmaf(d0, cv[6], fmaf(d1, cv[7], d2 * cv[8]));
        float nz = -Z;
        float h = fmaf(248.0f, __fdiv_rn(-Y, nz), 112.0f);
        float w = fmaf(248.0f, __fdiv_rn(X, nz), 112.0f);
        if (isnan(h)) h = 0.0f;
        if (isnan(w)) w = 0.0f;
        h = fminf(fmaxf(h, 0.0f), 223.0f);
        w = fminf(fmaxf(w, 0.0f), 223.0f);
        int h0 = (int)(h * 0.25f),    w0 = (int)(w * 0.25f);
        int h1 = (int)(h * 0.125f),   w1 = (int)(w * 0.125f);
        int h2 = (int)(h * 0.0625f),  w2 = (int)(w * 0.0625f);
        int h3 = (int)(h * 0.03125f), w3 = (int)(w * 0.03125f);
        sbase[v][0] = (h0 * 56 + w0) * 64;
        sbase[v][1] = 200704 + (h1 * 28 + w1) * 128;
        sbase[v][2] = 301056 + (h2 * 14 + w2) * 256;
        sbase[v][3] = 351232 + (h3 * 7 + w3) * 512;
        float inv = (v == 0) ? in0 : (v == 1) ? in1 : in2;
        sinp[v] = inv;
        // stage row-local index m=v at buf[4 + m - head]; for m < head also store direct
        buf[4 + v - head] = inv;
        if (v < head) __stcs(&out[base + v], inv);
    }
    __syncthreads();

    int b00 = sbase[0][0], b01 = sbase[0][1], b02 = sbase[0][2], b03 = sbase[0][3];
    int b10 = sbase[1][0], b11 = sbase[1][1], b12 = sbase[1][2], b13 = sbase[1][3];
    int b20 = sbase[2][0], b21 = sbase[2][1], b22 = sbase[2][2], b23 = sbase[2][3];

    // stage outputs: row-local index m = 3 + c (+960*sec) at buf[4 + m - head]
    float* smax = buf + 4 + 3 - head;

    #pragma unroll
    for (int it = 0; it < 4; it++) {
        int c = tid + it * 256;
        if (c >= 960) break;
        int i0, i1, i2;
        if (c < 64)       { i0 = b00 + c;       i1 = b10 + c;       i2 = b20 + c; }
        else if (c < 192) { int l = c - 64;  i0 = b01 + l; i1 = b11 + l; i2 = b21 + l; }
        else if (c < 448) { int l = c - 192; i0 = b02 + l; i1 = b12 + l; i2 = b22 + l; }
        else              { int l = c - 448; i0 = b03 + l; i1 = b13 + l; i2 = b23 + l; }
        float a = __ldg(&g_scratch[i0]);
        float b = __ldg(&g_scratch[i1]);
        float d = __ldg(&g_scratch[i2]);
        float mx = fmaxf(a, fmaxf(b, d));
        float mn = (a + b + d) * (1.0f / 3.0f);
        float e0 = a - mn, e1 = b - mn, e2 = d - mn;
        float sd = sqrtf((e0 * e0 + e1 * e1 + e2 * e2) * (1.0f / 3.0f));
        smax[c] = mx;
        smax[960 + c] = mn;
        smax[1920 + c] = sd;
    }
    __syncthreads();

    // tail: t = 3 - head floats at row-local m in [head + 2880, 2883)
    int t = 3 - head;
    if (tid < t)
        __stcs(&out[base + head + 2880 + tid], buf[4 + 2880 + tid]);

    // TMA bulk store of the aligned interior: global [base+head, base+head+2880),
    // src buf+4 (16B aligned), 11520 bytes (multiple of 16).
    if (tid == 0) {
        asm volatile("fence.proxy.async.shared::cta;" ::: "memory");
        unsigned int saddr = (unsigned int)__cvta_generic_to_shared(buf + 4);
        const float* gptr = out + base + head;
        asm volatile(
            "cp.async.bulk.global.shared::cta.bulk_group [%0], [%1], %2;"
            :: "l"(gptr), "r"(saddr), "r"(11520)
            : "memory");
        asm volatile("cp.async.bulk.commit_group;" ::: "memory");
        asm volatile("cp.async.bulk.wait_group 0;" ::: "memory");
    }
}

extern "C" void kernel_launch(void* const* d_in, const int* in_sizes, int n_in,
                              void* d_out, int out_size) {
    const float* inputs  = (const float*)d_in[0];
    const float* cameras = (const float*)d_in[1];
    const float* f0 = (const float*)d_in[2];
    const float* f1 = (const float*)d_in[3];
    const float* f2 = (const float*)d_in[4];
    const float* f3 = (const float*)d_in[5];
    float* out = (float*)d_out;

    int n = in_sizes[0] / 3;

    prep_kernel<<<(376320 + 255) / 256, 256>>>(f0, f1, f2, f3, cameras);
    main_kernel<<<n, 256>>>(inputs, out);
}

// round 7
// speedup vs baseline: 1.0763x; 1.0763x over previous
#include <cuda_runtime.h>
#include <math.h>

#define OUT_COLS 2883

// scratch: batch-0 features transposed to [H,W,C], concatenated per scale
//   s0: [56*56,64]  @ 0        s1: [28*28,128] @ 200704
//   s2: [14*14,256] @ 301056   s3: [7*7,512]   @ 351232
__device__ float g_scratch[376320];
// consts: [0..8] Minv[d][k], [9..11] o0; per view v at 12+v*12: c[v][k][d], o_v at +9..11
__device__ float g_consts[12 + 3 * 12];

// Fused: feature transpose (all blocks) + camera constants (block 0, threads 0-2)
__global__ void prep_kernel(const float* __restrict__ f0,
                            const float* __restrict__ f1,
                            const float* __restrict__ f2,
                            const float* __restrict__ f3,
                            const float* __restrict__ cameras) {
    if (blockIdx.x == 0 && threadIdx.x < 3) {
        const float PIF = 3.14159274101257324f;
        int v = threadIdx.x;
        float th = cameras[v * 5 + 0] * (PIF / 180.0f);
        float ph = cameras[v * 5 + 1] * (PIF / 180.0f);
        float r  = cameras[v * 5 + 3];
        float camy = r * sinf(ph);
        float lens = r * cosf(ph);
        float camx = lens * cosf(th);
        float camz = lens * sinf(th);
        float Z[3] = {camx, camy, camz};
        float Y[3] = {camy * cosf(th + PIF), lens, camy * sinf(th + PIF)};
        float X[3] = {Y[1] * Z[2] - Y[2] * Z[1],
                      Y[2] * Z[0] - Y[0] * Z[2],
                      Y[0] * Z[1] - Y[1] * Z[0]};
        float nx = sqrtf(X[0]*X[0] + X[1]*X[1] + X[2]*X[2]);
        float ny = sqrtf(Y[0]*Y[0] + Y[1]*Y[1] + Y[2]*Y[2]);
        float nz = sqrtf(Z[0]*Z[0] + Z[1]*Z[1] + Z[2]*Z[2]);
        float cn[3][3];
        for (int d = 0; d < 3; d++) {
            cn[0][d] = X[d] / nx;
            cn[1][d] = Y[d] / ny;
            cn[2][d] = Z[d] / nz;
        }
        for (int k = 0; k < 3; k++)
            for (int d = 0; d < 3; d++)
                g_consts[12 + v * 12 + k * 3 + d] = cn[k][d];
        for (int d = 0; d < 3; d++)
            g_consts[12 + v * 12 + 9 + d] = Z[d];

        if (v == 0) {
            double A[3][3];
            for (int i = 0; i < 3; i++)
                for (int j = 0; j < 3; j++)
                    A[i][j] = (double)cn[j][i];
            double det = A[0][0] * (A[1][1]*A[2][2] - A[1][2]*A[2][1])
                       + A[0][1] * (A[1][2]*A[2][0] - A[1][0]*A[2][2])
                       + A[0][2] * (A[1][0]*A[2][1] - A[1][1]*A[2][0]);
            double inv[3][3];
            inv[0][0] = (A[1][1]*A[2][2] - A[1][2]*A[2][1]) / det;
            inv[0][1] = (A[0][2]*A[2][1] - A[0][1]*A[2][2]) / det;
            inv[0][2] = (A[0][1]*A[1][2] - A[0][2]*A[1][1]) / det;
            inv[1][0] = (A[1][2]*A[2][0] - A[1][0]*A[2][2]) / det;
            inv[1][1] = (A[0][0]*A[2][2] - A[0][2]*A[2][0]) / det;
            inv[1][2] = (A[0][2]*A[1][0] - A[0][0]*A[1][2]) / det;
            inv[2][0] = (A[1][0]*A[2][1] - A[1][1]*A[2][0]) / det;
            inv[2][1] = (A[0][1]*A[2][0] - A[0][0]*A[2][1]) / det;
            inv[2][2] = (A[0][0]*A[1][1] - A[0][1]*A[1][0]) / det;
            for (int d = 0; d < 3; d++)
                for (int k = 0; k < 3; k++)
                    g_consts[d * 3 + k] = (float)inv[d][k];
            for (int d = 0; d < 3; d++)
                g_consts[9 + d] = Z[d];
        }
    }

    int i = blockIdx.x * blockDim.x + threadIdx.x;
    if (i >= 376320) return;
    float v;
    if (i < 200704)      { int c = i & 63;  int p = i >> 6;                 v = f0[c * 3136 + p]; }
    else if (i < 301056) { int l = i - 200704; int c = l & 127; int p = l >> 7; v = f1[c * 784 + p]; }
    else if (i < 351232) { int l = i - 301056; int c = l & 255; int p = l >> 8; v = f2[c * 196 + p]; }
    else                 { int l = i - 351232; int c = l & 511; int p = l >> 9; v = f3[c * 49 + p]; }
    g_scratch[i] = v;
}

// gather one channel's (a,b,d) with cache split: s0-s2 -> .cg, s3 -> .ca
__device__ __forceinline__ void gather3(int c,
                                        int b00, int b01, int b02, int b03,
                                        int b10, int b11, int b12, int b13,
                                        int b20, int b21, int b22, int b23,
                                        float& a, float& b, float& d) {
    if (c < 64) {
        a = __ldcg(&g_scratch[b00 + c]); b = __ldcg(&g_scratch[b10 + c]); d = __ldcg(&g_scratch[b20 + c]);
    } else if (c < 192) {
        int l = c - 64;
        a = __ldcg(&g_scratch[b01 + l]); b = __ldcg(&g_scratch[b11 + l]); d = __ldcg(&g_scratch[b21 + l]);
    } else if (c < 448) {
        int l = c - 192;
        a = __ldcg(&g_scratch[b02 + l]); b = __ldcg(&g_scratch[b12 + l]); d = __ldcg(&g_scratch[b22 + l]);
    } else {
        int l = c - 448;
        a = __ldca(&g_scratch[b03 + l]); b = __ldca(&g_scratch[b13 + l]); d = __ldca(&g_scratch[b23 + l]);
    }
}

__device__ __forceinline__ void stats(float a, float b, float d,
                                      float& mx, float& mn, float& sd) {
    mx = fmaxf(a, fmaxf(b, d));
    mn = (a + b + d) * (1.0f / 3.0f);
    float e0 = a - mn, e1 = b - mn, e2 = d - mn;
    sd = sqrtf((e0 * e0 + e1 * e1 + e2 * e2) * (1.0f / 3.0f));
}

__global__ __launch_bounds__(256) void main_kernel(const float* __restrict__ inputs,
                                                   float* __restrict__ out) {
    __shared__ int sbase[3][4];
    int row = blockIdx.x;
    int tid = threadIdx.x;
    size_t base = (size_t)row * OUT_COLS;

    if (tid < 3) {
        int v = tid;
        float in0 = inputs[row * 3 + 0];
        float in1 = inputs[row * 3 + 1];
        float in2 = inputs[row * 3 + 2];
        const float* C = g_consts;
        float po[3];
        #pragma unroll
        for (int k = 0; k < 3; k++)
            po[k] = fmaf(in0, C[0 * 3 + k],
                    fmaf(in1, C[1 * 3 + k],
                    fmaf(in2, C[2 * 3 + k], C[9 + k])));
        const float* cv = C + 12 + v * 12;
        float d0 = po[0] - cv[9];
        float d1 = po[1] - cv[10];
        float d2 = po[2] - cv[11];
        float X = fmaf(d0, cv[0], fmaf(d1, cv[1], d2 * cv[2]));
        float Y = fmaf(d0, cv[3], fmaf(d1, cv[4], d2 * cv[5]));
        float Z = fmaf(d0, cv[6], fmaf(d1, cv[7], d2 * cv[8]));
        float nz = -Z;
        float h = fmaf(248.0f, __fdiv_rn(-Y, nz), 112.0f);
        float w = fmaf(248.0f, __fdiv_rn(X, nz), 112.0f);
        if (isnan(h)) h = 0.0f;
        if (isnan(w)) w = 0.0f;
        h = fminf(fmaxf(h, 0.0f), 223.0f);
        w = fminf(fmaxf(w, 0.0f), 223.0f);
        int h0 = (int)(h * 0.25f),    w0 = (int)(w * 0.25f);
        int h1 = (int)(h * 0.125f),   w1 = (int)(w * 0.125f);
        int h2 = (int)(h * 0.0625f),  w2 = (int)(w * 0.0625f);
        int h3 = (int)(h * 0.03125f), w3 = (int)(w * 0.03125f);
        sbase[v][0] = (h0 * 56 + w0) * 64;
        sbase[v][1] = 200704 + (h1 * 28 + w1) * 128;
        sbase[v][2] = 301056 + (h2 * 14 + w2) * 256;
        sbase[v][3] = 351232 + (h3 * 7 + w3) * 512;
        __stcs(&out[base + v], (v == 0) ? in0 : (v == 1) ? in1 : in2);
    }
    __syncthreads();

    int b00 = sbase[0][0], b01 = sbase[0][1], b02 = sbase[0][2], b03 = sbase[0][3];
    int b10 = sbase[1][0], b11 = sbase[1][1], b12 = sbase[1][2], b13 = sbase[1][3];
    int b20 = sbase[2][0], b21 = sbase[2][1], b22 = sbase[2][2], b23 = sbase[2][3];

    float* orow = out + base + 3;              // channel 0 of section 0
    int gamma = (int)((base + 3) & 1);         // parity of first channel address

    if (gamma == 0) {
        // pairs {c0, c0+1}, c0 even: float2 loads AND float2 stores, both legal
        #pragma unroll
        for (int it = 0; it < 2; it++) {
            int p = tid + it * 256;
            if (p >= 480) break;
            int c0 = 2 * p;
            float2 a2, b2, d2;
            if (c0 < 64) {
                a2 = __ldcg((const float2*)&g_scratch[b00 + c0]);
                b2 = __ldcg((const float2*)&g_scratch[b10 + c0]);
                d2 = __ldcg((const float2*)&g_scratch[b20 + c0]);
            } else if (c0 < 192) {
                int l = c0 - 64;
                a2 = __ldcg((const float2*)&g_scratch[b01 + l]);
                b2 = __ldcg((const float2*)&g_scratch[b11 + l]);
                d2 = __ldcg((const float2*)&g_scratch[b21 + l]);
            } else if (c0 < 448) {
                int l = c0 - 192;
                a2 = __ldcg((const float2*)&g_scratch[b02 + l]);
                b2 = __ldcg((const float2*)&g_scratch[b12 + l]);
                d2 = __ldcg((const float2*)&g_scratch[b22 + l]);
            } else {
                int l = c0 - 448;
                a2 = __ldca((const float2*)&g_scratch[b03 + l]);
                b2 = __ldca((const float2*)&g_scratch[b13 + l]);
                d2 = __ldca((const float2*)&g_scratch[b23 + l]);
            }
            float2 mx2, mn2, sd2;
            stats(a2.x, b2.x, d2.x, mx2.x, mn2.x, sd2.x);
            stats(a2.y, b2.y, d2.y, mx2.y, mn2.y, sd2.y);
            __stcs((float2*)(orow + c0), mx2);
            __stcs((float2*)(orow + 960 + c0), mn2);
            __stcs((float2*)(orow + 1920 + c0), sd2);
        }
    } else {
        // pairs {c0, c0+1}, c0 odd (1..957): scalar loads, float2 stores
        #pragma unroll
        for (int it = 0; it < 2; it++) {
            int p = tid + it * 256;
            if (p >= 479) break;
            int c0 = 1 + 2 * p;
            float ax, bx, dx, ay, by, dy;
            gather3(c0,     b00,b01,b02,b03, b10,b11,b12,b13, b20,b21,b22,b23, ax, bx, dx);
            gather3(c0 + 1, b00,b01,b02,b03, b10,b11,b12,b13, b20,b21,b22,b23, ay, by, dy);
            float2 mx2, mn2, sd2;
            stats(ax, bx, dx, mx2.x, mn2.x, sd2.x);
            stats(ay, by, dy, mx2.y, mn2.y, sd2.y);
            __stcs((float2*)(orow + c0), mx2);
            __stcs((float2*)(orow + 960 + c0), mn2);
            __stcs((float2*)(orow + 1920 + c0), sd2);
        }
        // edge channels 0 and 959 (scalar)
        if (tid < 2) {
            int c = tid ? 959 : 0;
            float a, b, d;
            gather3(c, b00,b01,b02,b03, b10,b11,b12,b13, b20,b21,b22,b23, a, b, d);
            float mx, mn, sd;
            stats(a, b, d, mx, mn, sd);
            __stcs(&orow[c], mx);
            __stcs(&orow[960 + c], mn);
            __stcs(&orow[1920 + c], sd);
        }
    }
}

extern "C" void kernel_launch(void* const* d_in, const int* in_sizes, int n_in,
                              void* d_out, int out_size) {
    const float* inputs  = (const float*)d_in[0];
    const float* cameras = (const float*)d_in[1];
    const float* f0 = (const float*)d_in[2];
    const float* f1 = (const float*)d_in[3];
    const float* f2 = (const float*)d_in[4];
    const float* f3 = (const float*)d_in[5];
    float* out = (float*)d_out;

    int n = in_sizes[0] / 3;

    prep_kernel<<<(376320 + 255) / 256, 256>>>(f0, f1, f2, f3, cameras);
    main_kernel<<<n, 256>>>(inputs, out);
}

// round 8
// speedup vs baseline: 1.2266x; 1.1397x over previous
#include <cuda_runtime.h>
#include <math.h>

#define OUT_COLS 2883

// scratch: batch-0 features transposed to [H,W,C], concatenated per scale
//   s0: [56*56,64]  @ 0        s1: [28*28,128] @ 200704
//   s2: [14*14,256] @ 301056   s3: [7*7,512]   @ 351232
__device__ float g_scratch[376320];
// consts: [0..8] Minv[d][k], [9..11] o0; per view v at 12+v*12: c[v][k][d], o_v at +9..11
__device__ float g_consts[12 + 3 * 12];

// Fused: feature transpose (all blocks) + camera constants (block 0, threads 0-2)
__global__ void prep_kernel(const float* __restrict__ f0,
                            const float* __restrict__ f1,
                            const float* __restrict__ f2,
                            const float* __restrict__ f3,
                            const float* __restrict__ cameras) {
    if (blockIdx.x == 0 && threadIdx.x < 3) {
        const float PIF = 3.14159274101257324f;
        int v = threadIdx.x;
        float th = cameras[v * 5 + 0] * (PIF / 180.0f);
        float ph = cameras[v * 5 + 1] * (PIF / 180.0f);
        float r  = cameras[v * 5 + 3];
        float camy = r * sinf(ph);
        float lens = r * cosf(ph);
        float camx = lens * cosf(th);
        float camz = lens * sinf(th);
        float Z[3] = {camx, camy, camz};
        float Y[3] = {camy * cosf(th + PIF), lens, camy * sinf(th + PIF)};
        float X[3] = {Y[1] * Z[2] - Y[2] * Z[1],
                      Y[2] * Z[0] - Y[0] * Z[2],
                      Y[0] * Z[1] - Y[1] * Z[0]};
        float nx = sqrtf(X[0]*X[0] + X[1]*X[1] + X[2]*X[2]);
        float ny = sqrtf(Y[0]*Y[0] + Y[1]*Y[1] + Y[2]*Y[2]);
        float nz = sqrtf(Z[0]*Z[0] + Z[1]*Z[1] + Z[2]*Z[2]);
        float cn[3][3];
        for (int d = 0; d < 3; d++) {
            cn[0][d] = X[d] / nx;
            cn[1][d] = Y[d] / ny;
            cn[2][d] = Z[d] / nz;
        }
        for (int k = 0; k < 3; k++)
            for (int d = 0; d < 3; d++)
                g_consts[12 + v * 12 + k * 3 + d] = cn[k][d];
        for (int d = 0; d < 3; d++)
            g_consts[12 + v * 12 + 9 + d] = Z[d];

        if (v == 0) {
            double A[3][3];
            for (int i = 0; i < 3; i++)
                for (int j = 0; j < 3; j++)
                    A[i][j] = (double)cn[j][i];
            double det = A[0][0] * (A[1][1]*A[2][2] - A[1][2]*A[2][1])
                       + A[0][1] * (A[1][2]*A[2][0] - A[1][0]*A[2][2])
                       + A[0][2] * (A[1][0]*A[2][1] - A[1][1]*A[2][0]);
            double inv[3][3];
            inv[0][0] = (A[1][1]*A[2][2] - A[1][2]*A[2][1]) / det;
            inv[0][1] = (A[0][2]*A[2][1] - A[0][1]*A[2][2]) / det;
            inv[0][2] = (A[0][1]*A[1][2] - A[0][2]*A[1][1]) / det;
            inv[1][0] = (A[1][2]*A[2][0] - A[1][0]*A[2][2]) / det;
            inv[1][1] = (A[0][0]*A[2][2] - A[0][2]*A[2][0]) / det;
            inv[1][2] = (A[0][2]*A[1][0] - A[0][0]*A[1][2]) / det;
            inv[2][0] = (A[1][0]*A[2][1] - A[1][1]*A[2][0]) / det;
            inv[2][1] = (A[0][1]*A[2][0] - A[0][0]*A[2][1]) / det;
            inv[2][2] = (A[0][0]*A[1][1] - A[0][1]*A[1][0]) / det;
            for (int d = 0; d < 3; d++)
                for (int k = 0; k < 3; k++)
                    g_consts[d * 3 + k] = (float)inv[d][k];
            for (int d = 0; d < 3; d++)
                g_consts[9 + d] = Z[d];
        }
    }

    int i = blockIdx.x * blockDim.x + threadIdx.x;
    if (i >= 376320) return;
    float v;
    if (i < 200704)      { int c = i & 63;  int p = i >> 6;                 v = f0[c * 3136 + p]; }
    else if (i < 301056) { int l = i - 200704; int c = l & 127; int p = l >> 7; v = f1[c * 784 + p]; }
    else if (i < 351232) { int l = i - 301056; int c = l & 255; int p = l >> 8; v = f2[c * 196 + p]; }
    else                 { int l = i - 351232; int c = l & 511; int p = l >> 9; v = f3[c * 49 + p]; }
    g_scratch[i] = v;
}

// gather one channel's (a,b,d); bases come from shared (broadcast LDS, saves regs)
__device__ __forceinline__ void gather3s(int c, const int* sb,
                                         float& a, float& b, float& d) {
    int s, l;
    if (c < 64)       { s = 0; l = c; }
    else if (c < 192) { s = 1; l = c - 64; }
    else if (c < 448) { s = 2; l = c - 192; }
    else              { s = 3; l = c - 448; }
    a = __ldg(&g_scratch[sb[s] + l]);
    b = __ldg(&g_scratch[sb[4 + s] + l]);
    d = __ldg(&g_scratch[sb[8 + s] + l]);
}

__device__ __forceinline__ void stats(float a, float b, float d,
                                      float& mx, float& mn, float& sd) {
    mx = fmaxf(a, fmaxf(b, d));
    mn = (a + b + d) * (1.0f / 3.0f);
    float e0 = a - mn, e1 = b - mn, e2 = d - mn;
    sd = sqrtf((e0 * e0 + e1 * e1 + e2 * e2) * (1.0f / 3.0f));
}

__global__ __launch_bounds__(256, 8) void main_kernel(const float* __restrict__ inputs,
                                                      float* __restrict__ out) {
    __shared__ int sb[12];   // [v*4 + s]
    int row = blockIdx.x;
    int tid = threadIdx.x;
    size_t base = (size_t)row * OUT_COLS;

    if (tid < 3) {
        int v = tid;
        float in0 = inputs[row * 3 + 0];
        float in1 = inputs[row * 3 + 1];
        float in2 = inputs[row * 3 + 2];
        const float* C = g_consts;
        float po[3];
        #pragma unroll
        for (int k = 0; k < 3; k++)
            po[k] = fmaf(in0, C[0 * 3 + k],
                    fmaf(in1, C[1 * 3 + k],
                    fmaf(in2, C[2 * 3 + k], C[9 + k])));
        const float* cv = C + 12 + v * 12;
        float d0 = po[0] - cv[9];
        float d1 = po[1] - cv[10];
        float d2 = po[2] - cv[11];
        float X = fmaf(d0, cv[0], fmaf(d1, cv[1], d2 * cv[2]));
        float Y = fmaf(d0, cv[3], fmaf(d1, cv[4], d2 * cv[5]));
        float Z = fmaf(d0, cv[6], fmaf(d1, cv[7], d2 * cv[8]));
        float nz = -Z;
        float h = fmaf(248.0f, __fdiv_rn(-Y, nz), 112.0f);
        float w = fmaf(248.0f, __fdiv_rn(X, nz), 112.0f);
        if (isnan(h)) h = 0.0f;
        if (isnan(w)) w = 0.0f;
        h = fminf(fmaxf(h, 0.0f), 223.0f);
        w = fminf(fmaxf(w, 0.0f), 223.0f);
        int h0 = (int)(h * 0.25f),    w0 = (int)(w * 0.25f);
        int h1 = (int)(h * 0.125f),   w1 = (int)(w * 0.125f);
        int h2 = (int)(h * 0.0625f),  w2 = (int)(w * 0.0625f);
        int h3 = (int)(h * 0.03125f), w3 = (int)(w * 0.03125f);
        sb[v * 4 + 0] = (h0 * 56 + w0) * 64;
        sb[v * 4 + 1] = 200704 + (h1 * 28 + w1) * 128;
        sb[v * 4 + 2] = 301056 + (h2 * 14 + w2) * 256;
        sb[v * 4 + 3] = 351232 + (h3 * 7 + w3) * 512;
        __stcs(&out[base + v], (v == 0) ? in0 : (v == 1) ? in1 : in2);
    }
    __syncthreads();

    float* orow = out + base + 3;              // channel 0 of section 0
    int gamma = (int)((base + 3) & 1);         // 0 -> channel addr even at c=0
    int npairs = 480 - gamma;                  // pairs c0 = gamma + 2p

    #pragma unroll
    for (int it = 0; it < 2; it++) {
        int p = tid + it * 256;
        if (p < npairs) {
            int c0 = gamma + 2 * p;
            float ax, bx, dx, ay, by, dy;
            gather3s(c0,     sb, ax, bx, dx);
            gather3s(c0 + 1, sb, ay, by, dy);
            float2 mx2, mn2, sd2;
            stats(ax, bx, dx, mx2.x, mn2.x, sd2.x);
            stats(ay, by, dy, mx2.y, mn2.y, sd2.y);
            __stcs((float2*)(orow + c0), mx2);
            __stcs((float2*)(orow + 960 + c0), mn2);
            __stcs((float2*)(orow + 1920 + c0), sd2);
        }
    }

    // gamma=1 edge channels 0 and 959 (scalar)
    if (gamma && tid < 2) {
        int c = tid ? 959 : 0;
        float a, b, d;
        gather3s(c, sb, a, b, d);
        float mx, mn, sd;
        stats(a, b, d, mx, mn, sd);
        __stcs(&orow[c], mx);
        __stcs(&orow[960 + c], mn);
        __stcs(&orow[1920 + c], sd);
    }
}

extern "C" void kernel_launch(void* const* d_in, const int* in_sizes, int n_in,
                              void* d_out, int out_size) {
    const float* inputs  = (const float*)d_in[0];
    const float* cameras = (const float*)d_in[1];
    const float* f0 = (const float*)d_in[2];
    const float* f1 = (const float*)d_in[3];
    const float* f2 = (const float*)d_in[4];
    const float* f3 = (const float*)d_in[5];
    float* out = (float*)d_out;

    int n = in_sizes[0] / 3;

    prep_kernel<<<(376320 + 255) / 256, 256>>>(f0, f1, f2, f3, cameras);
    main_kernel<<<n, 256>>>(inputs, out);
}